// round 3
// baseline (speedup 1.0000x reference)
#include <cuda_runtime.h>
#include <math.h>

// Problem constants (fixed by setup_inputs)
#define B_   8
#define H_   12
#define LQ_  32
#define LF_  256
#define V_   32000
#define S_   4

// scratch (no cudaMalloc allowed)
__device__ float        g_probs[B_ * LF_];        // sigmoid(agg)*mask
__device__ float        g_u[(S_ - 1) * B_ * LF_]; // 6144 uniforms
__device__ unsigned int g_pack[B_ * LF_];         // 4 action bits (mask-gated)

// ---------------------------------------------------------------------------
// Kernel A: probs[b,f] = sigmoid( max_lq mean_h scores[b,h,lq,f] ) * mask[b,f]
// ---------------------------------------------------------------------------
__global__ void probs_kernel(const float* __restrict__ scores,
                             const float* __restrict__ attn_mask) {
    int t = blockIdx.x * blockDim.x + threadIdx.x;   // [0, 2048)
    if (t >= B_ * LF_) return;
    int b = t / LF_;
    int f = t % LF_;
    float best = -INFINITY;
    for (int lq = 0; lq < LQ_; lq++) {
        float s = 0.0f;
        #pragma unroll
        for (int h = 0; h < H_; h++) {
            s += scores[(((b * H_ + h) * LQ_) + lq) * LF_ + f];
        }
        best = fmaxf(best, s / 12.0f);
    }
    float p = 1.0f / (1.0f + expf(-best));
    g_probs[t] = p * attn_mask[t];
}

// ---------------------------------------------------------------------------
// Kernel B1: JAX threefry2x32, PARTITIONABLE mode (default since JAX 0.4.30).
// For 32-bit bits of flat size N: element i uses 64-bit counter i,
//   (o0, o1) = threefry2x32(key, (hi32(i), lo32(i)));  bits[i] = o0 ^ o1.
// key(42) -> (k0, k1) = (0, 42). Uniform: bitcast((bits>>9)|0x3f800000)-1, max 0.
// ---------------------------------------------------------------------------
__device__ __forceinline__ unsigned int rotl32(unsigned int x, int r) {
    return (x << r) | (x >> (32 - r));
}

__global__ void threefry_kernel() {
    int i = blockIdx.x * blockDim.x + threadIdx.x;   // [0, 6144)
    if (i >= (S_ - 1) * B_ * LF_) return;

    const unsigned int k0 = 0u;          // jax.random.key(42) -> [0, 42]
    const unsigned int k1 = 42u;
    const unsigned int k2 = 0x1BD11BDAu ^ k0 ^ k1;

    unsigned int x0 = 0u + k0;                 // hi32(i) == 0 for i < 2^32
    unsigned int x1 = (unsigned int)i + k1;    // lo32(i)

    const int rot0[4] = {13, 15, 26, 6};
    const int rot1[4] = {17, 29, 16, 24};

    #pragma unroll
    for (int r = 0; r < 4; r++) { x0 += x1; x1 = rotl32(x1, rot0[r]); x1 ^= x0; }
    x0 += k1; x1 += k2 + 1u;
    #pragma unroll
    for (int r = 0; r < 4; r++) { x0 += x1; x1 = rotl32(x1, rot1[r]); x1 ^= x0; }
    x0 += k2; x1 += k0 + 2u;
    #pragma unroll
    for (int r = 0; r < 4; r++) { x0 += x1; x1 = rotl32(x1, rot0[r]); x1 ^= x0; }
    x0 += k0; x1 += k1 + 3u;
    #pragma unroll
    for (int r = 0; r < 4; r++) { x0 += x1; x1 = rotl32(x1, rot1[r]); x1 ^= x0; }
    x0 += k1; x1 += k2 + 4u;
    #pragma unroll
    for (int r = 0; r < 4; r++) { x0 += x1; x1 = rotl32(x1, rot0[r]); x1 ^= x0; }
    x0 += k2; x1 += k0 + 5u;

    unsigned int bits = x0 ^ x1;   // 32-bit xor-fold (partitionable path)
    float u = __uint_as_float((bits >> 9) | 0x3f800000u) - 1.0f;
    g_u[i] = fmaxf(u, 0.0f);
}

// ---------------------------------------------------------------------------
// Kernel B2: actions [4,8,256] (float out), packed gate bits, logprobs [4,8].
// grid = (B_), block = (LF_)
// ---------------------------------------------------------------------------
__global__ void actions_kernel(const float* __restrict__ attn_mask,
                               float* __restrict__ out_logprobs,  // [4,8]
                               float* __restrict__ out_actions) { // [4,8,256]
    int b = blockIdx.x;
    int f = threadIdx.x;
    int t = b * LF_ + f;

    float p = g_probs[t];
    float m = attn_mask[t];

    float lp_if1 = logf(p);
    float lp_if0 = log1pf(-p);

    bool a[S_];
    a[0] = g_u[0 * (B_ * LF_) + t] < p;
    a[1] = g_u[1 * (B_ * LF_) + t] < p;
    a[2] = g_u[2 * (B_ * LF_) + t] < p;
    a[3] = p >= 0.5f;

    unsigned int pack = 0;
    float lp[S_];
    #pragma unroll
    for (int s = 0; s < S_; s++) {
        float af = a[s] ? 1.0f : 0.0f;
        out_actions[s * (B_ * LF_) + t] = af;
        lp[s] = a[s] ? lp_if1 : lp_if0;
        if (a[s] && m > 0.0f) pack |= (1u << s);
    }
    g_pack[t] = pack;

    // block reduction of lp[s] over the 256 f-positions
    __shared__ float red[LF_];
    #pragma unroll
    for (int s = 0; s < S_; s++) {
        red[f] = lp[s];
        __syncthreads();
        for (int off = LF_ / 2; off > 0; off >>= 1) {
            if (f < off) red[f] += red[f + off];
            __syncthreads();
        }
        if (f == 0) out_logprobs[s * B_ + b] = red[0];
        __syncthreads();
    }
}

// ---------------------------------------------------------------------------
// Kernel C (dominant): one streaming pass over f_logits.
// values[s,b,v] = max(q_max[b,v], log1p(max(0, max_{f active in s} fl[b,f,v])))
// grid = (V_/256, B_), block = 256
// ---------------------------------------------------------------------------
__global__ void __launch_bounds__(256) values_kernel(
        const float* __restrict__ q,       // [B, LQ, V]
        const float* __restrict__ fl,      // [B, LF, V]
        const float* __restrict__ qmask,   // [B, LQ]
        float* __restrict__ out_values) {  // [S, B, V]
    __shared__ unsigned int s_pack[LF_];
    __shared__ float        s_qmask[LQ_];

    int b = blockIdx.y;
    int tid = threadIdx.x;
    s_pack[tid] = g_pack[b * LF_ + tid];
    if (tid < LQ_) s_qmask[tid] = qmask[b * LQ_ + tid];
    __syncthreads();

    int v = blockIdx.x * 256 + tid;   // 125*256 == 32000, exact

    // q side
    float xq = -INFINITY;
    const float* qb = q + (size_t)b * LQ_ * V_ + v;
    #pragma unroll
    for (int lq = 0; lq < LQ_; lq++) {
        float x = qb[(size_t)lq * V_];
        if (s_qmask[lq] > 0.0f) xq = fmaxf(xq, x);
    }
    float qmax = log1pf(fmaxf(xq, 0.0f));

    // f side: single streaming pass, 4 predicated maxes
    float x0 = -INFINITY, x1 = -INFINITY, x2 = -INFINITY, x3 = -INFINITY;
    const float* fb = fl + (size_t)b * LF_ * V_ + v;
    #pragma unroll 8
    for (int f = 0; f < LF_; f++) {
        float x = fb[(size_t)f * V_];
        unsigned int pk = s_pack[f];
        if (pk & 1u) x0 = fmaxf(x0, x);
        if (pk & 2u) x1 = fmaxf(x1, x);
        if (pk & 4u) x2 = fmaxf(x2, x);
        if (pk & 8u) x3 = fmaxf(x3, x);
    }

    size_t base = (size_t)b * V_ + v;
    out_values[0 * (size_t)(B_ * V_) + base] = fmaxf(qmax, log1pf(fmaxf(x0, 0.0f)));
    out_values[1 * (size_t)(B_ * V_) + base] = fmaxf(qmax, log1pf(fmaxf(x1, 0.0f)));
    out_values[2 * (size_t)(B_ * V_) + base] = fmaxf(qmax, log1pf(fmaxf(x2, 0.0f)));
    out_values[3 * (size_t)(B_ * V_) + base] = fmaxf(qmax, log1pf(fmaxf(x3, 0.0f)));
}

// ---------------------------------------------------------------------------
extern "C" void kernel_launch(void* const* d_in, const int* in_sizes, int n_in,
                              void* d_out, int out_size) {
    // Resolve inputs by element count — robust to pytree/dict key ordering.
    const float* attention_scores = 0;
    const float* q_logits = 0;
    const float* f_logits = 0;
    const float* q_mask = 0;
    const float* attention_mask = 0;
    for (int i = 0; i < n_in; i++) {
        switch (in_sizes[i]) {
            case 786432:   attention_scores = (const float*)d_in[i]; break;
            case 8192000:  q_logits         = (const float*)d_in[i]; break;
            case 65536000: f_logits         = (const float*)d_in[i]; break;
            case 256:      q_mask           = (const float*)d_in[i]; break;
            case 2048:     attention_mask   = (const float*)d_in[i]; break;
            default: break; // samples (1) ignored; S_=4 hardcoded
        }
    }
    (void)out_size;

    float* out = (float*)d_out;
    // output layout (tuple order): values [4,8,32000] | logprobs [4,8] | actions [4,8,256]
    float* out_values   = out;
    float* out_logprobs = out + (size_t)S_ * B_ * V_;
    float* out_actions  = out + (size_t)S_ * B_ * V_ + S_ * B_;

    probs_kernel<<<(B_ * LF_ + 255) / 256, 256>>>(attention_scores, attention_mask);
    threefry_kernel<<<((S_ - 1) * B_ * LF_ + 255) / 256, 256>>>();
    actions_kernel<<<B_, LF_>>>(attention_mask, out_logprobs, out_actions);

    dim3 grid(V_ / 256, B_);
    values_kernel<<<grid, 256>>>(q_logits, f_logits, q_mask, out_values);
}

// round 4
// speedup vs baseline: 1.2055x; 1.2055x over previous
#include <cuda_runtime.h>
#include <math.h>

// Problem constants (fixed by setup_inputs)
#define B_   8
#define H_   12
#define LQ_  32
#define LF_  256
#define V_   32000
#define S_   4
#define V4_  (V_ / 4)          // 8000 float4 per (b, row)

// scratch (no cudaMalloc allowed)
__device__ unsigned int g_agg[B_ * LF_];          // monotone-encoded max_lq(mean_h)
__device__ float        g_u[(S_ - 1) * B_ * LF_]; // 6144 uniforms
__device__ unsigned int g_pack[B_ * LF_];         // 4 action bits (mask-gated)

// monotone float<->uint encoding so atomicMax(uint) == max(float)
__device__ __forceinline__ unsigned int enc_f(float x) {
    unsigned int u = __float_as_uint(x);
    return (u & 0x80000000u) ? ~u : (u | 0x80000000u);
}
__device__ __forceinline__ float dec_f(unsigned int k) {
    unsigned int u = (k & 0x80000000u) ? (k ^ 0x80000000u) : ~k;
    return __uint_as_float(u);
}

// ---------------------------------------------------------------------------
// Kernel 1: JAX threefry2x32, partitionable mode; also inits g_agg.
//   (o0,o1) = threefry2x32((0,42), (0, i));  bits = o0 ^ o1
//   u = bitcast((bits>>9)|0x3f800000) - 1, clamped at 0
// ---------------------------------------------------------------------------
__device__ __forceinline__ unsigned int rotl32(unsigned int x, int r) {
    return (x << r) | (x >> (32 - r));
}

__global__ void threefry_kernel() {
    int i = blockIdx.x * blockDim.x + threadIdx.x;   // [0, 6144)
    if (i >= (S_ - 1) * B_ * LF_) return;
    if (i < B_ * LF_) g_agg[i] = 0u;                 // 0 < enc(-inf): safe init

    const unsigned int k0 = 0u;
    const unsigned int k1 = 42u;
    const unsigned int k2 = 0x1BD11BDAu ^ k0 ^ k1;

    unsigned int x0 = 0u + k0;                 // hi32(i) == 0
    unsigned int x1 = (unsigned int)i + k1;    // lo32(i)

    const int rot0[4] = {13, 15, 26, 6};
    const int rot1[4] = {17, 29, 16, 24};

    #pragma unroll
    for (int r = 0; r < 4; r++) { x0 += x1; x1 = rotl32(x1, rot0[r]); x1 ^= x0; }
    x0 += k1; x1 += k2 + 1u;
    #pragma unroll
    for (int r = 0; r < 4; r++) { x0 += x1; x1 = rotl32(x1, rot1[r]); x1 ^= x0; }
    x0 += k2; x1 += k0 + 2u;
    #pragma unroll
    for (int r = 0; r < 4; r++) { x0 += x1; x1 = rotl32(x1, rot0[r]); x1 ^= x0; }
    x0 += k0; x1 += k1 + 3u;
    #pragma unroll
    for (int r = 0; r < 4; r++) { x0 += x1; x1 = rotl32(x1, rot1[r]); x1 ^= x0; }
    x0 += k1; x1 += k2 + 4u;
    #pragma unroll
    for (int r = 0; r < 4; r++) { x0 += x1; x1 = rotl32(x1, rot0[r]); x1 ^= x0; }
    x0 += k2; x1 += k0 + 5u;

    unsigned int bits = x0 ^ x1;
    float u = __uint_as_float((bits >> 9) | 0x3f800000u) - 1.0f;
    g_u[i] = fmaxf(u, 0.0f);
}

// ---------------------------------------------------------------------------
// Kernel 2: partial agg. grid = B_*LQ_ (256 blocks), block = LF_ (256).
// Block (b,lq): thread f sums 12 heads (same order as before), /12.0f,
// atomicMax into g_agg[b,f]. Fully order-independent max.
// ---------------------------------------------------------------------------
__global__ void __launch_bounds__(LF_) probs_partial_kernel(
        const float* __restrict__ scores) {
    int blk = blockIdx.x;
    int b = blk / LQ_;
    int lq = blk % LQ_;
    int f = threadIdx.x;

    const float* base = scores + (((size_t)b * H_) * LQ_ + lq) * LF_ + f;
    float s = 0.0f;
    #pragma unroll
    for (int h = 0; h < H_; h++) s += base[(size_t)h * LQ_ * LF_];
    float m = s / 12.0f;
    atomicMax(&g_agg[b * LF_ + f], enc_f(m));
}

// ---------------------------------------------------------------------------
// Kernel 3: actions [4,8,256], packed gate bits, logprobs [4,8].
// grid = B_, block = LF_
// ---------------------------------------------------------------------------
__global__ void actions_kernel(const float* __restrict__ attn_mask,
                               float* __restrict__ out_logprobs,  // [4,8]
                               float* __restrict__ out_actions) { // [4,8,256]
    int b = blockIdx.x;
    int f = threadIdx.x;
    int t = b * LF_ + f;

    float best = dec_f(g_agg[t]);
    float p = 1.0f / (1.0f + expf(-best));
    float m = attn_mask[t];
    p = p * m;

    float lp_if1 = logf(p);
    float lp_if0 = log1pf(-p);

    bool a[S_];
    a[0] = g_u[0 * (B_ * LF_) + t] < p;
    a[1] = g_u[1 * (B_ * LF_) + t] < p;
    a[2] = g_u[2 * (B_ * LF_) + t] < p;
    a[3] = p >= 0.5f;

    unsigned int pack = 0;
    float lp[S_];
    #pragma unroll
    for (int s = 0; s < S_; s++) {
        out_actions[s * (B_ * LF_) + t] = a[s] ? 1.0f : 0.0f;
        lp[s] = a[s] ? lp_if1 : lp_if0;
        if (a[s] && m > 0.0f) pack |= (1u << s);
    }
    g_pack[t] = pack;

    __shared__ float red[LF_];
    #pragma unroll
    for (int s = 0; s < S_; s++) {
        red[f] = lp[s];
        __syncthreads();
        for (int off = LF_ / 2; off > 0; off >>= 1) {
            if (f < off) red[f] += red[f + off];
            __syncthreads();
        }
        if (f == 0) out_logprobs[s * B_ + b] = red[0];
        __syncthreads();
    }
}

// ---------------------------------------------------------------------------
// Kernel 4 (dominant): float4 streaming pass over f_logits.
// grid = (ceil(8000/256)=32, B_), block = 256; one thread per (b, 4 v's)
// ---------------------------------------------------------------------------
__device__ __forceinline__ float4 max4(float4 a, float4 b) {
    a.x = fmaxf(a.x, b.x); a.y = fmaxf(a.y, b.y);
    a.z = fmaxf(a.z, b.z); a.w = fmaxf(a.w, b.w);
    return a;
}
__device__ __forceinline__ float4 l1prelu4(float4 a) {
    a.x = log1pf(fmaxf(a.x, 0.0f)); a.y = log1pf(fmaxf(a.y, 0.0f));
    a.z = log1pf(fmaxf(a.z, 0.0f)); a.w = log1pf(fmaxf(a.w, 0.0f));
    return a;
}

__global__ void __launch_bounds__(256) values_kernel(
        const float* __restrict__ q,       // [B, LQ, V]
        const float* __restrict__ fl,      // [B, LF, V]
        const float* __restrict__ qmask,   // [B, LQ]
        float* __restrict__ out_values) {  // [S, B, V]
    __shared__ unsigned int s_pack[LF_];
    __shared__ float        s_qmask[LQ_];

    int b = blockIdx.y;
    int tid = threadIdx.x;
    s_pack[tid] = g_pack[b * LF_ + tid];
    if (tid < LQ_) s_qmask[tid] = qmask[b * LQ_ + tid];
    __syncthreads();

    int v4 = blockIdx.x * 256 + tid;
    if (v4 >= V4_) return;

    const float4 NEG4 = make_float4(-INFINITY, -INFINITY, -INFINITY, -INFINITY);

    // q side
    float4 xq = NEG4;
    const float4* qb = (const float4*)(q + (size_t)b * LQ_ * V_) + v4;
    #pragma unroll
    for (int lq = 0; lq < LQ_; lq++) {
        float4 x = qb[(size_t)lq * V4_];
        if (s_qmask[lq] > 0.0f) xq = max4(xq, x);
    }
    float4 qmax = l1prelu4(xq);

    // f side: streaming max, 4 samples, predicated
    float4 a0 = NEG4, a1 = NEG4, a2 = NEG4, a3 = NEG4;
    const float4* fb = (const float4*)(fl + (size_t)b * LF_ * V_) + v4;
    #pragma unroll 4
    for (int f = 0; f < LF_; f++) {
        float4 x = fb[(size_t)f * V4_];
        unsigned int pk = s_pack[f];
        if (pk & 1u) a0 = max4(a0, x);
        if (pk & 2u) a1 = max4(a1, x);
        if (pk & 4u) a2 = max4(a2, x);
        if (pk & 8u) a3 = max4(a3, x);
    }

    size_t base = (size_t)b * V4_ + v4;
    float4* out4 = (float4*)out_values;
    out4[0 * (size_t)(B_ * V4_) + base] = max4(qmax, l1prelu4(a0));
    out4[1 * (size_t)(B_ * V4_) + base] = max4(qmax, l1prelu4(a1));
    out4[2 * (size_t)(B_ * V4_) + base] = max4(qmax, l1prelu4(a2));
    out4[3 * (size_t)(B_ * V4_) + base] = max4(qmax, l1prelu4(a3));
}

// ---------------------------------------------------------------------------
extern "C" void kernel_launch(void* const* d_in, const int* in_sizes, int n_in,
                              void* d_out, int out_size) {
    // Resolve inputs by element count — robust to pytree/dict key ordering.
    const float* attention_scores = 0;
    const float* q_logits = 0;
    const float* f_logits = 0;
    const float* q_mask = 0;
    const float* attention_mask = 0;
    for (int i = 0; i < n_in; i++) {
        switch (in_sizes[i]) {
            case 786432:   attention_scores = (const float*)d_in[i]; break;
            case 8192000:  q_logits         = (const float*)d_in[i]; break;
            case 65536000: f_logits         = (const float*)d_in[i]; break;
            case 256:      q_mask           = (const float*)d_in[i]; break;
            case 2048:     attention_mask   = (const float*)d_in[i]; break;
            default: break; // samples (1) ignored; S_=4 hardcoded
        }
    }
    (void)out_size;

    float* out = (float*)d_out;
    // output layout (tuple order): values [4,8,32000] | logprobs [4,8] | actions [4,8,256]
    float* out_values   = out;
    float* out_logprobs = out + (size_t)S_ * B_ * V_;
    float* out_actions  = out + (size_t)S_ * B_ * V_ + S_ * B_;

    threefry_kernel<<<((S_ - 1) * B_ * LF_ + 255) / 256, 256>>>();
    probs_partial_kernel<<<B_ * LQ_, LF_>>>(attention_scores);
    actions_kernel<<<B_, LF_>>>(attention_mask, out_logprobs, out_actions);

    dim3 grid((V4_ + 255) / 256, B_);
    values_kernel<<<grid, 256>>>(q_logits, f_logits, q_mask, out_values);
}